// round 9
// baseline (speedup 1.0000x reference)
#include <cuda_runtime.h>
#include <cuda_fp16.h>
#include <cstdint>
#include <math.h>

#define NB 64
#define NT 256
#define ND 512

// fp16 scratch: transposed + sqrt(w)-scaled + RN-rounded, layout [b][d][t]
__device__ __half g_rh[(size_t)NB * ND * NT];
__device__ __half g_ih[(size_t)NB * ND * NT];

// ---------- helpers ----------
__device__ __forceinline__ uint32_t s2u(const void* p) {
    uint32_t a;
    asm("{ .reg .u64 t; cvta.to.shared.u64 t, %1; cvt.u32.u64 %0, t; }" : "=r"(a) : "l"(p));
    return a;
}
__device__ __forceinline__ void cpa16(uint32_t dst, const void* src) {
    asm volatile("cp.async.cg.shared.global [%0], [%1], 16;" :: "r"(dst), "l"(src));
}
__device__ __forceinline__ void ldsm4(uint32_t r[4], uint32_t addr) {
    asm volatile("ldmatrix.sync.aligned.m8n8.x4.shared.b16 {%0,%1,%2,%3}, [%4];"
                 : "=r"(r[0]), "=r"(r[1]), "=r"(r[2]), "=r"(r[3]) : "r"(addr));
}
__device__ __forceinline__ void mma16816(float c[4], const uint32_t a[4],
                                         uint32_t b0, uint32_t b1) {
    asm volatile(
        "mma.sync.aligned.m16n8k16.row.col.f32.f16.f16.f32 "
        "{%0,%1,%2,%3}, {%4,%5,%6,%7}, {%8,%9}, {%0,%1,%2,%3};"
        : "+f"(c[0]), "+f"(c[1]), "+f"(c[2]), "+f"(c[3])
        : "r"(a[0]), "r"(a[1]), "r"(a[2]), "r"(a[3]), "r"(b0), "r"(b1));
}

// ---------- Pass 1: transpose + sqrt(w) scale + fp16 round ----------
__global__ void __launch_bounds__(256) prep_kernel(
    const float* __restrict__ real, const float* __restrict__ imag,
    const float* __restrict__ weight) {
    __shared__ float tr[32][33];
    __shared__ float ti[32][33];
    __shared__ float sw[32];
    int b = blockIdx.z;
    int d0 = blockIdx.x * 32, t0 = blockIdx.y * 32;
    int tid = threadIdx.x;
    int lx = tid & 31, ly = tid >> 5;  // ly 0..7
    if (tid < 32) sw[tid] = sqrtf(weight[b * NT + t0 + tid]);
    const float* rb = real + ((size_t)b * NT + t0) * ND + d0;
    const float* ib = imag + ((size_t)b * NT + t0) * ND + d0;
#pragma unroll
    for (int p = 0; p < 4; p++) {
        int t = p * 8 + ly;
        tr[t][lx] = rb[(size_t)t * ND + lx];
        ti[t][lx] = ib[(size_t)t * ND + lx];
    }
    __syncthreads();
    __half* orp = g_rh + ((size_t)b * ND + d0) * NT + t0;
    __half* oip = g_ih + ((size_t)b * ND + d0) * NT + t0;
    int dd = tid >> 4;   // 0..15
    int tp = tid & 15;   // t-pair
    float s0 = sw[2 * tp], s1 = sw[2 * tp + 1];
#pragma unroll
    for (int q = 0; q < 2; q++) {
        int d = q * 16 + dd;
        __half2 hr = __floats2half2_rn(tr[2 * tp][d] * s0, tr[2 * tp + 1][d] * s1);
        __half2 hi = __floats2half2_rn(ti[2 * tp][d] * s0, ti[2 * tp + 1][d] * s1);
        *reinterpret_cast<__half2*>(orp + (size_t)d * NT + 2 * tp) = hr;
        *reinterpret_cast<__half2*>(oip + (size_t)d * NT + 2 * tp) = hi;
    }
}

// ---------- Pass 2: fp16 mma.sync batched GEMM, symmetric tiles ----------
#define ROW_B 80
#define TILE_B (128 * ROW_B)      // 10240
#define STAGE_B (4 * TILE_B)      // 40960
#define NSTAGE 3
#define SMEM_REQ (NSTAGE * STAGE_B)  // 122880

__global__ void __launch_bounds__(256, 1) gemm_kernel(float* __restrict__ out) {
    extern __shared__ char smem[];
    uint32_t sb = s2u(smem);
    int tid = threadIdx.x, lane = tid & 31, wid = tid >> 5;
    int wm = wid & 3, wn = wid >> 2;  // 4 warps along M(128), 2 along N(128)
    int b = blockIdx.z;
    const int PDI[10] = {0, 0, 0, 0, 1, 1, 1, 2, 2, 3};
    const int PEI[10] = {0, 1, 2, 3, 1, 2, 3, 2, 3, 3};
    int di = PDI[blockIdx.x], ei = PEI[blockIdx.x];
    bool diag = (di == ei);
    int ntiles = diag ? 2 : 4;
    uint32_t bto = diag ? 0u : 2u * TILE_B;  // B tiles alias A tiles on diagonal

    const __half* srcs[4];
    srcs[0] = g_rh + ((size_t)b * ND + di * 128) * NT;
    srcs[1] = g_ih + ((size_t)b * ND + di * 128) * NT;
    srcs[2] = g_rh + ((size_t)b * ND + ei * 128) * NT;
    srcs[3] = g_ih + ((size_t)b * ND + ei * 128) * NT;

    int jr = tid & 3, rr = tid >> 2;  // 16B chunk in row / base row (0..63)

    auto issue = [&](int c, int s) {
        for (int m = 0; m < ntiles; m++) {
            uint32_t tb = sb + (uint32_t)s * STAGE_B + (uint32_t)m * TILE_B;
#pragma unroll
            for (int rep = 0; rep < 2; rep++) {
                int row = rep * 64 + rr;
                cpa16(tb + (uint32_t)(row * ROW_B + jr * 16),
                      srcs[m] + (size_t)row * NT + c * 32 + jr * 8);
            }
        }
        asm volatile("cp.async.commit_group;" ::: "memory");
    };

    float accS[2][8][4], accD[2][8][4];
#pragma unroll
    for (int mt = 0; mt < 2; mt++)
#pragma unroll
        for (int nt = 0; nt < 8; nt++)
#pragma unroll
            for (int q = 0; q < 4; q++) { accS[mt][nt][q] = 0.f; accD[mt][nt][q] = 0.f; }

    issue(0, 0);
    issue(1, 1);
    for (int c = 0; c < 8; c++) {
        int s = c % NSTAGE;
        if (c < 7) asm volatile("cp.async.wait_group 1;" ::: "memory");
        else       asm volatile("cp.async.wait_group 0;" ::: "memory");
        __syncthreads();
        if (c + 2 < 8) issue(c + 2, (c + 2) % NSTAGE);
        uint32_t stb = sb + (uint32_t)s * STAGE_B;
#pragma unroll
        for (int kk = 0; kk < 2; kk++) {
            int colb = kk * 32 + (lane >> 4) * 16;
            uint32_t rA[2][4], iA[2][4];
#pragma unroll
            for (int mt = 0; mt < 2; mt++) {
                int row = wm * 32 + mt * 16 + (lane & 15);
                ldsm4(rA[mt], stb + 0 * TILE_B + row * ROW_B + colb);
                ldsm4(iA[mt], stb + 1 * TILE_B + row * ROW_B + colb);
            }
            uint32_t rB[4][4], iB[4][4];
#pragma unroll
            for (int p = 0; p < 4; p++) {
                int row = wn * 64 + p * 16 + (lane & 15);
                ldsm4(rB[p], stb + bto + row * ROW_B + colb);
                ldsm4(iB[p], stb + bto + TILE_B + row * ROW_B + colb);
            }
            // S += r.r + i.i
#pragma unroll
            for (int mt = 0; mt < 2; mt++)
#pragma unroll
                for (int p = 0; p < 4; p++) {
                    mma16816(accS[mt][2 * p + 0], rA[mt], rB[p][0], rB[p][2]);
                    mma16816(accS[mt][2 * p + 1], rA[mt], rB[p][1], rB[p][3]);
                    mma16816(accS[mt][2 * p + 0], iA[mt], iB[p][0], iB[p][2]);
                    mma16816(accS[mt][2 * p + 1], iA[mt], iB[p][1], iB[p][3]);
                }
            // negate rA (fp16x2 sign flip), then D += i.r + (-r).i
#pragma unroll
            for (int mt = 0; mt < 2; mt++)
#pragma unroll
                for (int q = 0; q < 4; q++) rA[mt][q] ^= 0x80008000u;
#pragma unroll
            for (int mt = 0; mt < 2; mt++)
#pragma unroll
                for (int p = 0; p < 4; p++) {
                    mma16816(accD[mt][2 * p + 0], iA[mt], rB[p][0], rB[p][2]);
                    mma16816(accD[mt][2 * p + 1], iA[mt], rB[p][1], rB[p][3]);
                    mma16816(accD[mt][2 * p + 0], rA[mt], iB[p][0], iB[p][2]);
                    mma16816(accD[mt][2 * p + 1], rA[mt], iB[p][1], iB[p][3]);
                }
        }
    }

    // ---- Epilogue: direct tile (d rows, e cols) ----
    size_t ob = (size_t)NB * ND * ND;
#pragma unroll
    for (int mt = 0; mt < 2; mt++) {
        int gd = di * 128 + wm * 32 + mt * 16 + (lane >> 2);
#pragma unroll
        for (int nt = 0; nt < 8; nt++) {
            int ge = ei * 128 + wn * 64 + nt * 8 + (lane & 3) * 2;
            float* pr = out + ((size_t)b * ND + gd) * ND + ge;
            *reinterpret_cast<float2*>(pr) = make_float2(accS[mt][nt][0], accS[mt][nt][1]);
            *reinterpret_cast<float2*>(pr + 8 * ND) = make_float2(accS[mt][nt][2], accS[mt][nt][3]);
            float* pi = pr + ob;
            *reinterpret_cast<float2*>(pi) = make_float2(accD[mt][nt][0], accD[mt][nt][1]);
            *reinterpret_cast<float2*>(pi + 8 * ND) = make_float2(accD[mt][nt][2], accD[mt][nt][3]);
        }
    }

    // ---- Mirrored tile via SMEM transpose (off-diagonal only) ----
    if (!diag) {
        float* ts = reinterpret_cast<float*>(smem);  // stride 129 floats
        // S: out_r[e][d] = S[d][e]
        __syncthreads();
#pragma unroll
        for (int mt = 0; mt < 2; mt++) {
            int gdl = wm * 32 + mt * 16 + (lane >> 2);
#pragma unroll
            for (int nt = 0; nt < 8; nt++) {
                int gel = wn * 64 + nt * 8 + (lane & 3) * 2;
                ts[gdl * 129 + gel]           = accS[mt][nt][0];
                ts[gdl * 129 + gel + 1]       = accS[mt][nt][1];
                ts[(gdl + 8) * 129 + gel]     = accS[mt][nt][2];
                ts[(gdl + 8) * 129 + gel + 1] = accS[mt][nt][3];
            }
        }
        __syncthreads();
#pragma unroll
        for (int it = 0; it < 16; it++) {
            int e = (it & 3) * 32 + (tid >> 3);
            int d = ((it >> 2) * 8 + (tid & 7)) * 4;
            float4 v;
            v.x = ts[(d + 0) * 129 + e];
            v.y = ts[(d + 1) * 129 + e];
            v.z = ts[(d + 2) * 129 + e];
            v.w = ts[(d + 3) * 129 + e];
            *reinterpret_cast<float4*>(
                out + ((size_t)b * ND + ei * 128 + e) * ND + di * 128 + d) = v;
        }
        __syncthreads();
        // D: out_i[e][d] = -D[d][e]
#pragma unroll
        for (int mt = 0; mt < 2; mt++) {
            int gdl = wm * 32 + mt * 16 + (lane >> 2);
#pragma unroll
            for (int nt = 0; nt < 8; nt++) {
                int gel = wn * 64 + nt * 8 + (lane & 3) * 2;
                ts[gdl * 129 + gel]           = accD[mt][nt][0];
                ts[gdl * 129 + gel + 1]       = accD[mt][nt][1];
                ts[(gdl + 8) * 129 + gel]     = accD[mt][nt][2];
                ts[(gdl + 8) * 129 + gel + 1] = accD[mt][nt][3];
            }
        }
        __syncthreads();
#pragma unroll
        for (int it = 0; it < 16; it++) {
            int e = (it & 3) * 32 + (tid >> 3);
            int d = ((it >> 2) * 8 + (tid & 7)) * 4;
            float4 v;
            v.x = -ts[(d + 0) * 129 + e];
            v.y = -ts[(d + 1) * 129 + e];
            v.z = -ts[(d + 2) * 129 + e];
            v.w = -ts[(d + 3) * 129 + e];
            *reinterpret_cast<float4*>(
                out + ob + ((size_t)b * ND + ei * 128 + e) * ND + di * 128 + d) = v;
        }
    }
}

extern "C" void kernel_launch(void* const* d_in, const int* in_sizes, int n_in,
                              void* d_out, int out_size) {
    const float* real = (const float*)d_in[0];
    const float* imag = (const float*)d_in[1];
    const float* weight = (const float*)d_in[2];
    float* out = (float*)d_out;

    cudaFuncSetAttribute(gemm_kernel, cudaFuncAttributeMaxDynamicSharedMemorySize, SMEM_REQ);

    dim3 g1(ND / 32, NT / 32, NB);  // (16, 8, 64)
    prep_kernel<<<g1, 256>>>(real, imag, weight);

    dim3 g2(10, 1, NB);  // 10 (di<=ei) tile pairs x 64 batches = 640 CTAs
    gemm_kernel<<<g2, 256, SMEM_REQ>>>(out);
}

// round 12
// speedup vs baseline: 1.6306x; 1.6306x over previous
#include <cuda_runtime.h>
#include <cuda_fp16.h>
#include <cstdint>
#include <math.h>

#define NB 64
#define NT 256
#define ND 512

// fp16 scratch: sqrt(w)-scaled + RN-rounded, NATIVE layout [b][t][d]
__device__ __half g_rh[(size_t)NB * NT * ND];
__device__ __half g_ih[(size_t)NB * NT * ND];

// ---------- helpers ----------
__device__ __forceinline__ uint32_t s2u(const void* p) {
    uint32_t a;
    asm("{ .reg .u64 t; cvta.to.shared.u64 t, %1; cvt.u32.u64 %0, t; }" : "=r"(a) : "l"(p));
    return a;
}
__device__ __forceinline__ void cpa16(uint32_t dst, const void* src) {
    asm volatile("cp.async.cg.shared.global [%0], [%1], 16;" :: "r"(dst), "l"(src));
}
__device__ __forceinline__ void ldsm4t(uint32_t r[4], uint32_t addr) {
    asm volatile("ldmatrix.sync.aligned.m8n8.x4.trans.shared.b16 {%0,%1,%2,%3}, [%4];"
                 : "=r"(r[0]), "=r"(r[1]), "=r"(r[2]), "=r"(r[3]) : "r"(addr));
}
__device__ __forceinline__ void mma16816(float c[4], const uint32_t a[4],
                                         uint32_t b0, uint32_t b1) {
    asm volatile(
        "mma.sync.aligned.m16n8k16.row.col.f32.f16.f16.f32 "
        "{%0,%1,%2,%3}, {%4,%5,%6,%7}, {%8,%9}, {%0,%1,%2,%3};"
        : "+f"(c[0]), "+f"(c[1]), "+f"(c[2]), "+f"(c[3])
        : "r"(a[0]), "r"(a[1]), "r"(a[2]), "r"(a[3]), "r"(b0), "r"(b1));
}

// ---------- Pass 1: element-wise sqrt(w) scale + fp16 round (no transpose) ----------
__global__ void __launch_bounds__(128) prep_kernel(
    const float* __restrict__ real, const float* __restrict__ imag,
    const float* __restrict__ weight) {
    int row = blockIdx.x;  // b*NT + t
    float s = sqrtf(weight[row]);
    size_t base = (size_t)row * ND;
    int j = threadIdx.x;  // 0..127, 4 floats each
    float4 r = reinterpret_cast<const float4*>(real + base)[j];
    float4 im = reinterpret_cast<const float4*>(imag + base)[j];
    __half2 ra = __floats2half2_rn(r.x * s, r.y * s);
    __half2 rb = __floats2half2_rn(r.z * s, r.w * s);
    __half2 ia = __floats2half2_rn(im.x * s, im.y * s);
    __half2 ib = __floats2half2_rn(im.z * s, im.w * s);
    uint2 rv = make_uint2(*reinterpret_cast<uint32_t*>(&ra), *reinterpret_cast<uint32_t*>(&rb));
    uint2 iv = make_uint2(*reinterpret_cast<uint32_t*>(&ia), *reinterpret_cast<uint32_t*>(&ib));
    *reinterpret_cast<uint2*>(g_rh + base + j * 4) = rv;
    *reinterpret_cast<uint2*>(g_ih + base + j * 4) = iv;
}

// ---------- Pass 2: fp16 mma.sync, symmetric tiles, trans-ldmatrix ----------
#define KROW_B 272
#define TILE4_B (32 * KROW_B)        // 8704
#define STAGE_B (4 * TILE4_B)        // 34816
#define NSTAGE 3
#define SMEM_REQ (NSTAGE * STAGE_B)  // 104448

template <int NTILES>
__device__ __forceinline__ void mainloop(
    uint32_t sb, int tid, int lane, int wm, int wn,
    const __half* p0, const __half* p1, const __half* p2, const __half* p3,
    float (&accS)[2][8][4], float (&accD)[2][8][4]) {
    constexpr uint32_t bto = (NTILES == 2) ? 0u : 2u * TILE4_B;
    int jr = tid & 15, rr = tid >> 4;  // 16B chunk in 256B row / row base (0..15)
    const __half* bases[4] = {p0, p1, p2, p3};

    auto issue = [&](int c, int s) {
        uint32_t st = sb + (uint32_t)s * STAGE_B;
#pragma unroll
        for (int m = 0; m < NTILES; m++) {
#pragma unroll
            for (int rep = 0; rep < 2; rep++) {
                int row = rep * 16 + rr;
                cpa16(st + (uint32_t)m * TILE4_B + (uint32_t)(row * KROW_B + jr * 16),
                      bases[m] + (size_t)(c * 32 + row) * ND + jr * 8);
            }
        }
        asm volatile("cp.async.commit_group;" ::: "memory");
    };

    int kbase = (lane >> 4) * 8 + (lane & 7);
    int csel = ((lane >> 3) & 1) * 8;

    issue(0, 0);
    issue(1, 1);
    for (int c = 0; c < 8; c++) {
        int s = c % NSTAGE;
        if (c < 7) asm volatile("cp.async.wait_group 1;" ::: "memory");
        else       asm volatile("cp.async.wait_group 0;" ::: "memory");
        __syncthreads();
        if (c + 2 < 8) issue(c + 2, (c + 2) % NSTAGE);
        uint32_t stb = sb + (uint32_t)s * STAGE_B;
#pragma unroll
        for (int kk = 0; kk < 2; kk++) {
            uint32_t krow = (uint32_t)((kk * 16 + kbase) * KROW_B);
            uint32_t rA[2][4], iA[2][4];
#pragma unroll
            for (int mt = 0; mt < 2; mt++) {
                uint32_t co = (uint32_t)((wm * 32 + mt * 16 + csel) * 2);
                ldsm4t(rA[mt], stb + 0 * TILE4_B + krow + co);
                ldsm4t(iA[mt], stb + 1 * TILE4_B + krow + co);
            }
            uint32_t rB[4][4], iB[4][4];
#pragma unroll
            for (int p = 0; p < 4; p++) {
                uint32_t co = (uint32_t)((wn * 64 + p * 16 + csel) * 2);
                ldsm4t(rB[p], stb + bto + krow + co);
                ldsm4t(iB[p], stb + bto + TILE4_B + krow + co);
            }
            // S += r.r + i.i
#pragma unroll
            for (int mt = 0; mt < 2; mt++)
#pragma unroll
                for (int p = 0; p < 4; p++) {
                    mma16816(accS[mt][2 * p + 0], rA[mt], rB[p][0], rB[p][2]);
                    mma16816(accS[mt][2 * p + 1], rA[mt], rB[p][1], rB[p][3]);
                    mma16816(accS[mt][2 * p + 0], iA[mt], iB[p][0], iB[p][2]);
                    mma16816(accS[mt][2 * p + 1], iA[mt], iB[p][1], iB[p][3]);
                }
            // negate rA (fp16x2 sign flip), then D += i.r + (-r).i
#pragma unroll
            for (int mt = 0; mt < 2; mt++)
#pragma unroll
                for (int q = 0; q < 4; q++) rA[mt][q] ^= 0x80008000u;
#pragma unroll
            for (int mt = 0; mt < 2; mt++)
#pragma unroll
                for (int p = 0; p < 4; p++) {
                    mma16816(accD[mt][2 * p + 0], iA[mt], rB[p][0], rB[p][2]);
                    mma16816(accD[mt][2 * p + 1], iA[mt], rB[p][1], rB[p][3]);
                    mma16816(accD[mt][2 * p + 0], rA[mt], iB[p][0], iB[p][2]);
                    mma16816(accD[mt][2 * p + 1], rA[mt], iB[p][1], iB[p][3]);
                }
        }
    }
}

__global__ void __launch_bounds__(256, 1) gemm_kernel(float* __restrict__ out) {
    extern __shared__ char smem[];
    uint32_t sb = s2u(smem);
    int tid = threadIdx.x, lane = tid & 31, wid = tid >> 5;
    int wm = wid & 3, wn = wid >> 2;
    int b = blockIdx.z;
    int bx = blockIdx.x;
    const int ODI[6] = {0, 0, 0, 1, 1, 2};
    const int OEI[6] = {1, 2, 3, 2, 3, 3};
    bool diag = (bx >= 6);
    int di = diag ? (bx - 6) : ODI[bx];
    int ei = diag ? (bx - 6) : OEI[bx];

    const __half* a_r = g_rh + (size_t)b * NT * ND + di * 128;
    const __half* a_i = g_ih + (size_t)b * NT * ND + di * 128;
    const __half* b_r = g_rh + (size_t)b * NT * ND + ei * 128;
    const __half* b_i = g_ih + (size_t)b * NT * ND + ei * 128;

    float accS[2][8][4], accD[2][8][4];
#pragma unroll
    for (int mt = 0; mt < 2; mt++)
#pragma unroll
        for (int nt = 0; nt < 8; nt++)
#pragma unroll
            for (int q = 0; q < 4; q++) { accS[mt][nt][q] = 0.f; accD[mt][nt][q] = 0.f; }

    if (diag)
        mainloop<2>(sb, tid, lane, wm, wn, a_r, a_i, b_r, b_i, accS, accD);
    else
        mainloop<4>(sb, tid, lane, wm, wn, a_r, a_i, b_r, b_i, accS, accD);

    // ---- Epilogue: direct tile (d rows, e cols) ----
    size_t ob = (size_t)NB * ND * ND;
#pragma unroll
    for (int mt = 0; mt < 2; mt++) {
        int gd = di * 128 + wm * 32 + mt * 16 + (lane >> 2);
#pragma unroll
        for (int nt = 0; nt < 8; nt++) {
            int ge = ei * 128 + wn * 64 + nt * 8 + (lane & 3) * 2;
            float* pr = out + ((size_t)b * ND + gd) * ND + ge;
            *reinterpret_cast<float2*>(pr) = make_float2(accS[mt][nt][0], accS[mt][nt][1]);
            *reinterpret_cast<float2*>(pr + 8 * ND) = make_float2(accS[mt][nt][2], accS[mt][nt][3]);
            float* pi = pr + ob;
            *reinterpret_cast<float2*>(pi) = make_float2(accD[mt][nt][0], accD[mt][nt][1]);
            *reinterpret_cast<float2*>(pi + 8 * ND) = make_float2(accD[mt][nt][2], accD[mt][nt][3]);
        }
    }

    // ---- Mirrored tile via SMEM transpose (off-diagonal only) ----
    if (!diag) {
        float* ts = reinterpret_cast<float*>(smem);  // stride 129 floats
        __syncthreads();
#pragma unroll
        for (int mt = 0; mt < 2; mt++) {
            int gdl = wm * 32 + mt * 16 + (lane >> 2);
#pragma unroll
            for (int nt = 0; nt < 8; nt++) {
                int gel = wn * 64 + nt * 8 + (lane & 3) * 2;
                ts[gdl * 129 + gel]           = accS[mt][nt][0];
                ts[gdl * 129 + gel + 1]       = accS[mt][nt][1];
                ts[(gdl + 8) * 129 + gel]     = accS[mt][nt][2];
                ts[(gdl + 8) * 129 + gel + 1] = accS[mt][nt][3];
            }
        }
        __syncthreads();
#pragma unroll
        for (int it = 0; it < 16; it++) {
            int e = (it & 3) * 32 + (tid >> 3);
            int d = ((it >> 2) * 8 + (tid & 7)) * 4;
            float4 v;
            v.x = ts[(d + 0) * 129 + e];
            v.y = ts[(d + 1) * 129 + e];
            v.z = ts[(d + 2) * 129 + e];
            v.w = ts[(d + 3) * 129 + e];
            *reinterpret_cast<float4*>(
                out + ((size_t)b * ND + ei * 128 + e) * ND + di * 128 + d) = v;
        }
        __syncthreads();
#pragma unroll
        for (int mt = 0; mt < 2; mt++) {
            int gdl = wm * 32 + mt * 16 + (lane >> 2);
#pragma unroll
            for (int nt = 0; nt < 8; nt++) {
                int gel = wn * 64 + nt * 8 + (lane & 3) * 2;
                ts[gdl * 129 + gel]           = accD[mt][nt][0];
                ts[gdl * 129 + gel + 1]       = accD[mt][nt][1];
                ts[(gdl + 8) * 129 + gel]     = accD[mt][nt][2];
                ts[(gdl + 8) * 129 + gel + 1] = accD[mt][nt][3];
            }
        }
        __syncthreads();
#pragma unroll
        for (int it = 0; it < 16; it++) {
            int e = (it & 3) * 32 + (tid >> 3);
            int d = ((it >> 2) * 8 + (tid & 7)) * 4;
            float4 v;
            v.x = -ts[(d + 0) * 129 + e];
            v.y = -ts[(d + 1) * 129 + e];
            v.z = -ts[(d + 2) * 129 + e];
            v.w = -ts[(d + 3) * 129 + e];
            *reinterpret_cast<float4*>(
                out + ob + ((size_t)b * ND + ei * 128 + e) * ND + di * 128 + d) = v;
        }
    }
}

extern "C" void kernel_launch(void* const* d_in, const int* in_sizes, int n_in,
                              void* d_out, int out_size) {
    const float* real = (const float*)d_in[0];
    const float* imag = (const float*)d_in[1];
    const float* weight = (const float*)d_in[2];
    float* out = (float*)d_out;

    cudaFuncSetAttribute(gemm_kernel, cudaFuncAttributeMaxDynamicSharedMemorySize, SMEM_REQ);

    prep_kernel<<<NB * NT, 128>>>(real, imag, weight);

    dim3 g2(10, 1, NB);  // 6 off-diag + 4 diag tile pairs, x 64 batches
    gemm_kernel<<<g2, 256, SMEM_REQ>>>(out);
}

// round 13
// speedup vs baseline: 1.6399x; 1.0057x over previous
#include <cuda_runtime.h>
#include <cuda_fp16.h>
#include <cstdint>
#include <math.h>

#define NB 64
#define NT 256
#define ND 512

// fp16 scratch: sqrt(w)-scaled + RN-rounded, NATIVE layout [b][t][d]
__device__ __half g_rh[(size_t)NB * NT * ND];
__device__ __half g_ih[(size_t)NB * NT * ND];

// ---------- helpers ----------
__device__ __forceinline__ uint32_t s2u(const void* p) {
    uint32_t a;
    asm("{ .reg .u64 t; cvta.to.shared.u64 t, %1; cvt.u32.u64 %0, t; }" : "=r"(a) : "l"(p));
    return a;
}
__device__ __forceinline__ void cpa16(uint32_t dst, const void* src) {
    asm volatile("cp.async.cg.shared.global [%0], [%1], 16;" :: "r"(dst), "l"(src));
}
__device__ __forceinline__ void ldsm4t(uint32_t r[4], uint32_t addr) {
    asm volatile("ldmatrix.sync.aligned.m8n8.x4.trans.shared.b16 {%0,%1,%2,%3}, [%4];"
                 : "=r"(r[0]), "=r"(r[1]), "=r"(r[2]), "=r"(r[3]) : "r"(addr));
}
__device__ __forceinline__ void mma16816(float c[4], const uint32_t a[4],
                                         uint32_t b0, uint32_t b1) {
    asm volatile(
        "mma.sync.aligned.m16n8k16.row.col.f32.f16.f16.f32 "
        "{%0,%1,%2,%3}, {%4,%5,%6,%7}, {%8,%9}, {%0,%1,%2,%3};"
        : "+f"(c[0]), "+f"(c[1]), "+f"(c[2]), "+f"(c[3])
        : "r"(a[0]), "r"(a[1]), "r"(a[2]), "r"(a[3]), "r"(b0), "r"(b1));
}

// ---------- Pass 1: element-wise sqrt(w) scale + fp16 round ----------
__global__ void __launch_bounds__(128) prep_kernel(
    const float* __restrict__ real, const float* __restrict__ imag,
    const float* __restrict__ weight) {
    int row = blockIdx.x;  // b*NT + t
    float s = sqrtf(weight[row]);
    size_t base = (size_t)row * ND;
    int j = threadIdx.x;
    float4 r = reinterpret_cast<const float4*>(real + base)[j];
    float4 im = reinterpret_cast<const float4*>(imag + base)[j];
    __half2 ra = __floats2half2_rn(r.x * s, r.y * s);
    __half2 rb = __floats2half2_rn(r.z * s, r.w * s);
    __half2 ia = __floats2half2_rn(im.x * s, im.y * s);
    __half2 ib = __floats2half2_rn(im.z * s, im.w * s);
    uint2 rv = make_uint2(*reinterpret_cast<uint32_t*>(&ra), *reinterpret_cast<uint32_t*>(&rb));
    uint2 iv = make_uint2(*reinterpret_cast<uint32_t*>(&ia), *reinterpret_cast<uint32_t*>(&ib));
    *reinterpret_cast<uint2*>(g_rh + base + j * 4) = rv;
    *reinterpret_cast<uint2*>(g_ih + base + j * 4) = iv;
}

// ---------- Pass 2: fp16 mma.sync, 512 threads, symmetric tiles ----------
#define KROW_B 272
#define TILE4_B (32 * KROW_B)        // 8704
#define STAGE_B (4 * TILE4_B)        // 34816
#define NSTAGE 3
#define SMEM_REQ (NSTAGE * STAGE_B)  // 104448 (>= 128*129*4 transpose buf)

template <int NTILES>
__device__ __forceinline__ void mainloop(
    uint32_t sb, int tid, int lane, int wm, int wn,
    const __half* p0, const __half* p1, const __half* p2, const __half* p3,
    float (&accS)[2][4][4], float (&accD)[2][4][4]) {
    constexpr uint32_t bto = (NTILES == 2) ? 0u : 2u * TILE4_B;
    int jr = tid & 15, rr = tid >> 4;  // 16B chunk / k-row (0..31); 512 thr = 1 tile
    const __half* bases[4] = {p0, p1, p2, p3};

    auto issue = [&](int c, int s) {
        uint32_t st = sb + (uint32_t)s * STAGE_B;
#pragma unroll
        for (int m = 0; m < NTILES; m++) {
            cpa16(st + (uint32_t)m * TILE4_B + (uint32_t)(rr * KROW_B + jr * 16),
                  bases[m] + (size_t)(c * 32 + rr) * ND + jr * 8);
        }
        asm volatile("cp.async.commit_group;" ::: "memory");
    };

    int kbase = (lane >> 4) * 8 + (lane & 7);
    int csel = ((lane >> 3) & 1) * 8;

    issue(0, 0);
    issue(1, 1);
    for (int c = 0; c < 8; c++) {
        int s = c % NSTAGE;
        if (c < 7) asm volatile("cp.async.wait_group 1;" ::: "memory");
        else       asm volatile("cp.async.wait_group 0;" ::: "memory");
        __syncthreads();
        if (c + 2 < 8) issue(c + 2, (c + 2) % NSTAGE);
        uint32_t stb = sb + (uint32_t)s * STAGE_B;
#pragma unroll
        for (int kk = 0; kk < 2; kk++) {
            uint32_t krow = (uint32_t)((kk * 16 + kbase) * KROW_B);
            uint32_t rA[2][4], iA[2][4];
#pragma unroll
            for (int mt = 0; mt < 2; mt++) {
                uint32_t co = (uint32_t)((wm * 32 + mt * 16 + csel) * 2);
                ldsm4t(rA[mt], stb + 0 * TILE4_B + krow + co);
                ldsm4t(iA[mt], stb + 1 * TILE4_B + krow + co);
            }
            uint32_t rB[2][4], iB[2][4];
#pragma unroll
            for (int p = 0; p < 2; p++) {
                uint32_t co = (uint32_t)((wn * 32 + p * 16 + csel) * 2);
                ldsm4t(rB[p], stb + bto + krow + co);
                ldsm4t(iB[p], stb + bto + TILE4_B + krow + co);
            }
            // S += r.r + i.i
#pragma unroll
            for (int mt = 0; mt < 2; mt++)
#pragma unroll
                for (int p = 0; p < 2; p++) {
                    mma16816(accS[mt][2 * p + 0], rA[mt], rB[p][0], rB[p][2]);
                    mma16816(accS[mt][2 * p + 1], rA[mt], rB[p][1], rB[p][3]);
                    mma16816(accS[mt][2 * p + 0], iA[mt], iB[p][0], iB[p][2]);
                    mma16816(accS[mt][2 * p + 1], iA[mt], iB[p][1], iB[p][3]);
                }
            // negate rA (fp16x2 sign flip), then D += i.r + (-r).i
#pragma unroll
            for (int mt = 0; mt < 2; mt++)
#pragma unroll
                for (int q = 0; q < 4; q++) rA[mt][q] ^= 0x80008000u;
#pragma unroll
            for (int mt = 0; mt < 2; mt++)
#pragma unroll
                for (int p = 0; p < 2; p++) {
                    mma16816(accD[mt][2 * p + 0], iA[mt], rB[p][0], rB[p][2]);
                    mma16816(accD[mt][2 * p + 1], iA[mt], rB[p][1], rB[p][3]);
                    mma16816(accD[mt][2 * p + 0], rA[mt], iB[p][0], iB[p][2]);
                    mma16816(accD[mt][2 * p + 1], rA[mt], iB[p][1], iB[p][3]);
                }
        }
    }
}

__global__ void __launch_bounds__(512, 1) gemm_kernel(float* __restrict__ out) {
    extern __shared__ char smem[];
    uint32_t sb = s2u(smem);
    int tid = threadIdx.x, lane = tid & 31, wid = tid >> 5;
    int wm = wid & 3, wn = wid >> 2;  // 4x4 warp grid, 32x32 per warp
    int b = blockIdx.z;
    int bx = blockIdx.x;
    const int ODI[6] = {0, 0, 0, 1, 1, 2};
    const int OEI[6] = {1, 2, 3, 2, 3, 3};
    bool diag = (bx >= 6);
    int di = diag ? (bx - 6) : ODI[bx];
    int ei = diag ? (bx - 6) : OEI[bx];

    const __half* a_r = g_rh + (size_t)b * NT * ND + di * 128;
    const __half* a_i = g_ih + (size_t)b * NT * ND + di * 128;
    const __half* b_r = g_rh + (size_t)b * NT * ND + ei * 128;
    const __half* b_i = g_ih + (size_t)b * NT * ND + ei * 128;

    float accS[2][4][4], accD[2][4][4];
#pragma unroll
    for (int mt = 0; mt < 2; mt++)
#pragma unroll
        for (int nt = 0; nt < 4; nt++)
#pragma unroll
            for (int q = 0; q < 4; q++) { accS[mt][nt][q] = 0.f; accD[mt][nt][q] = 0.f; }

    if (diag)
        mainloop<2>(sb, tid, lane, wm, wn, a_r, a_i, b_r, b_i, accS, accD);
    else
        mainloop<4>(sb, tid, lane, wm, wn, a_r, a_i, b_r, b_i, accS, accD);

    // ---- Epilogue: direct tile (d rows, e cols) ----
    size_t ob = (size_t)NB * ND * ND;
#pragma unroll
    for (int mt = 0; mt < 2; mt++) {
        int gd = di * 128 + wm * 32 + mt * 16 + (lane >> 2);
#pragma unroll
        for (int nt = 0; nt < 4; nt++) {
            int ge = ei * 128 + wn * 32 + nt * 8 + (lane & 3) * 2;
            float* pr = out + ((size_t)b * ND + gd) * ND + ge;
            *reinterpret_cast<float2*>(pr) = make_float2(accS[mt][nt][0], accS[mt][nt][1]);
            *reinterpret_cast<float2*>(pr + 8 * ND) = make_float2(accS[mt][nt][2], accS[mt][nt][3]);
            float* pi = pr + ob;
            *reinterpret_cast<float2*>(pi) = make_float2(accD[mt][nt][0], accD[mt][nt][1]);
            *reinterpret_cast<float2*>(pi + 8 * ND) = make_float2(accD[mt][nt][2], accD[mt][nt][3]);
        }
    }

    // ---- Mirrored tile via SMEM transpose (off-diagonal only) ----
    if (!diag) {
        float* ts = reinterpret_cast<float*>(smem);  // stride 129 floats
        __syncthreads();
        // S: out_r[e][d] = S[d][e]
#pragma unroll
        for (int mt = 0; mt < 2; mt++) {
            int gdl = wm * 32 + mt * 16 + (lane >> 2);
#pragma unroll
            for (int nt = 0; nt < 4; nt++) {
                int gel = wn * 32 + nt * 8 + (lane & 3) * 2;
                ts[gdl * 129 + gel]           = accS[mt][nt][0];
                ts[gdl * 129 + gel + 1]       = accS[mt][nt][1];
                ts[(gdl + 8) * 129 + gel]     = accS[mt][nt][2];
                ts[(gdl + 8) * 129 + gel + 1] = accS[mt][nt][3];
            }
        }
        __syncthreads();
#pragma unroll
        for (int it = 0; it < 8; it++) {
            int e = tid >> 2;
            int d = (it * 4 + (tid & 3)) * 4;
            float4 v;
            v.x = ts[(d + 0) * 129 + e];
            v.y = ts[(d + 1) * 129 + e];
            v.z = ts[(d + 2) * 129 + e];
            v.w = ts[(d + 3) * 129 + e];
            *reinterpret_cast<float4*>(
                out + ((size_t)b * ND + ei * 128 + e) * ND + di * 128 + d) = v;
        }
        __syncthreads();
        // D: out_i[e][d] = -D[d][e]
#pragma unroll
        for (int mt = 0; mt < 2; mt++) {
            int gdl = wm * 32 + mt * 16 + (lane >> 2);
#pragma unroll
            for (int nt = 0; nt < 4; nt++) {
                int gel = wn * 32 + nt * 8 + (lane & 3) * 2;
                ts[gdl * 129 + gel]           = accD[mt][nt][0];
                ts[gdl * 129 + gel + 1]       = accD[mt][nt][1];
                ts[(gdl + 8) * 129 + gel]     = accD[mt][nt][2];
                ts[(gdl + 8) * 129 + gel + 1] = accD[mt][nt][3];
            }
        }
        __syncthreads();
#pragma unroll
        for (int it = 0; it < 8; it++) {
            int e = tid >> 2;
            int d = (it * 4 + (tid & 3)) * 4;
            float4 v;
            v.x = -ts[(d + 0) * 129 + e];
            v.y = -ts[(d + 1) * 129 + e];
            v.z = -ts[(d + 2) * 129 + e];
            v.w = -ts[(d + 3) * 129 + e];
            *reinterpret_cast<float4*>(
                out + ob + ((size_t)b * ND + ei * 128 + e) * ND + di * 128 + d) = v;
        }
    }
}

extern "C" void kernel_launch(void* const* d_in, const int* in_sizes, int n_in,
                              void* d_out, int out_size) {
    const float* real = (const float*)d_in[0];
    const float* imag = (const float*)d_in[1];
    const float* weight = (const float*)d_in[2];
    float* out = (float*)d_out;

    cudaFuncSetAttribute(gemm_kernel, cudaFuncAttributeMaxDynamicSharedMemorySize, SMEM_REQ);

    prep_kernel<<<NB * NT, 128>>>(real, imag, weight);

    dim3 g2(10, 1, NB);  // 6 off-diag + 4 diag tile pairs, x 64 batches
    gemm_kernel<<<g2, 512, SMEM_REQ>>>(out);
}

// round 14
// speedup vs baseline: 1.7189x; 1.0482x over previous
#include <cuda_runtime.h>
#include <cuda_fp16.h>
#include <cstdint>
#include <math.h>

#define NB 64
#define NT 256
#define ND 512

// fp16 scratch: sqrt(w)-scaled + RN-rounded, NATIVE layout [b][t][d]
__device__ __half g_rh[(size_t)NB * NT * ND];
__device__ __half g_ih[(size_t)NB * NT * ND];

// ---------- helpers ----------
__device__ __forceinline__ uint32_t s2u(const void* p) {
    uint32_t a;
    asm("{ .reg .u64 t; cvta.to.shared.u64 t, %1; cvt.u32.u64 %0, t; }" : "=r"(a) : "l"(p));
    return a;
}
__device__ __forceinline__ void cpa16(uint32_t dst, const void* src) {
    asm volatile("cp.async.cg.shared.global [%0], [%1], 16;" :: "r"(dst), "l"(src));
}
__device__ __forceinline__ void ldsm4t(uint32_t r[4], uint32_t addr) {
    asm volatile("ldmatrix.sync.aligned.m8n8.x4.trans.shared.b16 {%0,%1,%2,%3}, [%4];"
                 : "=r"(r[0]), "=r"(r[1]), "=r"(r[2]), "=r"(r[3]) : "r"(addr));
}
__device__ __forceinline__ void mma16816(float c[4], const uint32_t a[4],
                                         uint32_t b0, uint32_t b1) {
    asm volatile(
        "mma.sync.aligned.m16n8k16.row.col.f32.f16.f16.f32 "
        "{%0,%1,%2,%3}, {%4,%5,%6,%7}, {%8,%9}, {%0,%1,%2,%3};"
        : "+f"(c[0]), "+f"(c[1]), "+f"(c[2]), "+f"(c[3])
        : "r"(a[0]), "r"(a[1]), "r"(a[2]), "r"(a[3]), "r"(b0), "r"(b1));
}

// ---------- Pass 1: element-wise sqrt(w) scale + fp16 round ----------
__global__ void __launch_bounds__(128) prep_kernel(
    const float* __restrict__ real, const float* __restrict__ imag,
    const float* __restrict__ weight) {
    int row = blockIdx.x;  // b*NT + t
    float s = sqrtf(weight[row]);
    size_t base = (size_t)row * ND;
    int j = threadIdx.x;
    float4 r = reinterpret_cast<const float4*>(real + base)[j];
    float4 im = reinterpret_cast<const float4*>(imag + base)[j];
    __half2 ra = __floats2half2_rn(r.x * s, r.y * s);
    __half2 rb = __floats2half2_rn(r.z * s, r.w * s);
    __half2 ia = __floats2half2_rn(im.x * s, im.y * s);
    __half2 ib = __floats2half2_rn(im.z * s, im.w * s);
    uint2 rv = make_uint2(*reinterpret_cast<uint32_t*>(&ra), *reinterpret_cast<uint32_t*>(&rb));
    uint2 iv = make_uint2(*reinterpret_cast<uint32_t*>(&ia), *reinterpret_cast<uint32_t*>(&ib));
    *reinterpret_cast<uint2*>(g_rh + base + j * 4) = rv;
    *reinterpret_cast<uint2*>(g_ih + base + j * 4) = iv;
}

// ---------- Pass 2: fp16 mma.sync, 128x64 tiles, 2 CTAs/SM ----------
#define AROW_B 272              // 128 cols * 2B + 16 pad
#define BROW_B 144              // 64 cols * 2B + 16 pad
#define ATILE_B (32 * AROW_B)   // 8704
#define BTILE_B (32 * BROW_B)   // 4608
#define AOFF0 0
#define AOFF1 ATILE_B
#define BOFF0 (2 * ATILE_B)
#define BOFF1 (2 * ATILE_B + BTILE_B)
#define STAGE_B (2 * ATILE_B + 2 * BTILE_B)  // 26624
#define NSTAGE 3
#define SMEM_REQ (NSTAGE * STAGE_B)          // 79872 (>= 128*65*4 = 33280)

__global__ void __launch_bounds__(256, 2) gemm_kernel(float* __restrict__ out) {
    extern __shared__ char smem[];
    uint32_t sb = s2u(smem);
    int tid = threadIdx.x, lane = tid & 31, wid = tid >> 5;
    int wm = wid & 3, wn = wid >> 2;  // 4 x 2 warp grid, 32x32 per warp
    int b = blockIdx.z;
    int bx = blockIdx.x;
    const int ODI[6] = {0, 0, 0, 1, 1, 2};
    const int OEI[6] = {1, 2, 3, 2, 3, 3};
    bool mirror = (bx < 12);
    int di, ei, h;
    if (mirror) { di = ODI[bx >> 1]; ei = OEI[bx >> 1]; h = bx & 1; }
    else        { int q = bx - 12; di = q >> 1; ei = q >> 1; h = q & 1; }

    const __half* a_r = g_rh + (size_t)b * NT * ND + di * 128;
    const __half* a_i = g_ih + (size_t)b * NT * ND + di * 128;
    const __half* b_r = g_rh + (size_t)b * NT * ND + ei * 128 + h * 64;
    const __half* b_i = g_ih + (size_t)b * NT * ND + ei * 128 + h * 64;

    int jr = tid & 15, rr = tid >> 4;   // A: 16B chunk / row base (0..15)
    int jb = tid & 7,  rb_ = tid >> 3;  // B: 16B chunk / row (0..31)

    auto issue = [&](int c, int s) {
        uint32_t st = sb + (uint32_t)s * STAGE_B;
#pragma unroll
        for (int rep = 0; rep < 2; rep++) {
            int row = rep * 16 + rr;
            cpa16(st + AOFF0 + (uint32_t)(row * AROW_B + jr * 16),
                  a_r + (size_t)(c * 32 + row) * ND + jr * 8);
            cpa16(st + AOFF1 + (uint32_t)(row * AROW_B + jr * 16),
                  a_i + (size_t)(c * 32 + row) * ND + jr * 8);
        }
        cpa16(st + BOFF0 + (uint32_t)(rb_ * BROW_B + jb * 16),
              b_r + (size_t)(c * 32 + rb_) * ND + jb * 8);
        cpa16(st + BOFF1 + (uint32_t)(rb_ * BROW_B + jb * 16),
              b_i + (size_t)(c * 32 + rb_) * ND + jb * 8);
        asm volatile("cp.async.commit_group;" ::: "memory");
    };

    float accS[2][4][4], accD[2][4][4];
#pragma unroll
    for (int mt = 0; mt < 2; mt++)
#pragma unroll
        for (int nt = 0; nt < 4; nt++)
#pragma unroll
            for (int q = 0; q < 4; q++) { accS[mt][nt][q] = 0.f; accD[mt][nt][q] = 0.f; }

    int kbase = (lane >> 4) * 8 + (lane & 7);
    int csel = ((lane >> 3) & 1) * 8;

    issue(0, 0);
    issue(1, 1);
    for (int c = 0; c < 8; c++) {
        int s = c % NSTAGE;
        if (c < 7) asm volatile("cp.async.wait_group 1;" ::: "memory");
        else       asm volatile("cp.async.wait_group 0;" ::: "memory");
        __syncthreads();
        if (c + 2 < 8) issue(c + 2, (c + 2) % NSTAGE);
        uint32_t stb = sb + (uint32_t)s * STAGE_B;
#pragma unroll
        for (int kk = 0; kk < 2; kk++) {
            uint32_t krowA = (uint32_t)((kk * 16 + kbase) * AROW_B);
            uint32_t krowB = (uint32_t)((kk * 16 + kbase) * BROW_B);
            uint32_t rA[2][4], iA[2][4];
#pragma unroll
            for (int mt = 0; mt < 2; mt++) {
                uint32_t co = (uint32_t)((wm * 32 + mt * 16 + csel) * 2);
                ldsm4t(rA[mt], stb + AOFF0 + krowA + co);
                ldsm4t(iA[mt], stb + AOFF1 + krowA + co);
            }
            uint32_t rB[2][4], iB[2][4];
#pragma unroll
            for (int p = 0; p < 2; p++) {
                uint32_t co = (uint32_t)((wn * 32 + p * 16 + csel) * 2);
                ldsm4t(rB[p], stb + BOFF0 + krowB + co);
                ldsm4t(iB[p], stb + BOFF1 + krowB + co);
            }
            // S += r.r + i.i
#pragma unroll
            for (int mt = 0; mt < 2; mt++)
#pragma unroll
                for (int p = 0; p < 2; p++) {
                    mma16816(accS[mt][2 * p + 0], rA[mt], rB[p][0], rB[p][2]);
                    mma16816(accS[mt][2 * p + 1], rA[mt], rB[p][1], rB[p][3]);
                    mma16816(accS[mt][2 * p + 0], iA[mt], iB[p][0], iB[p][2]);
                    mma16816(accS[mt][2 * p + 1], iA[mt], iB[p][1], iB[p][3]);
                }
            // negate rA (fp16x2 sign flip), then D += i.r + (-r).i
#pragma unroll
            for (int mt = 0; mt < 2; mt++)
#pragma unroll
                for (int q = 0; q < 4; q++) rA[mt][q] ^= 0x80008000u;
#pragma unroll
            for (int mt = 0; mt < 2; mt++)
#pragma unroll
                for (int p = 0; p < 2; p++) {
                    mma16816(accD[mt][2 * p + 0], iA[mt], rB[p][0], rB[p][2]);
                    mma16816(accD[mt][2 * p + 1], iA[mt], rB[p][1], rB[p][3]);
                    mma16816(accD[mt][2 * p + 0], rA[mt], iB[p][0], iB[p][2]);
                    mma16816(accD[mt][2 * p + 1], rA[mt], iB[p][1], iB[p][3]);
                }
        }
    }

    // ---- Epilogue: direct tile (d rows, e cols) ----
    size_t ob = (size_t)NB * ND * ND;
    int ecol0 = ei * 128 + h * 64;
#pragma unroll
    for (int mt = 0; mt < 2; mt++) {
        int gd = di * 128 + wm * 32 + mt * 16 + (lane >> 2);
#pragma unroll
        for (int nt = 0; nt < 4; nt++) {
            int ge = ecol0 + wn * 32 + nt * 8 + (lane & 3) * 2;
            float* pr = out + ((size_t)b * ND + gd) * ND + ge;
            *reinterpret_cast<float2*>(pr) = make_float2(accS[mt][nt][0], accS[mt][nt][1]);
            *reinterpret_cast<float2*>(pr + 8 * ND) = make_float2(accS[mt][nt][2], accS[mt][nt][3]);
            float* pi = pr + ob;
            *reinterpret_cast<float2*>(pi) = make_float2(accD[mt][nt][0], accD[mt][nt][1]);
            *reinterpret_cast<float2*>(pi + 8 * ND) = make_float2(accD[mt][nt][2], accD[mt][nt][3]);
        }
    }

    // ---- Mirrored tile via SMEM transpose (off-diagonal only) ----
    if (mirror) {
        float* ts = reinterpret_cast<float*>(smem);  // [128][65] floats
        __syncthreads();
        // S: out_r[e][d] = S[d][e]
#pragma unroll
        for (int mt = 0; mt < 2; mt++) {
            int gdl = wm * 32 + mt * 16 + (lane >> 2);
#pragma unroll
            for (int nt = 0; nt < 4; nt++) {
                int gel = wn * 32 + nt * 8 + (lane & 3) * 2;
                ts[gdl * 65 + gel]           = accS[mt][nt][0];
                ts[gdl * 65 + gel + 1]       = accS[mt][nt][1];
                ts[(gdl + 8) * 65 + gel]     = accS[mt][nt][2];
                ts[(gdl + 8) * 65 + gel + 1] = accS[mt][nt][3];
            }
        }
        __syncthreads();
#pragma unroll
        for (int it = 0; it < 8; it++) {
            int e = tid >> 2;                 // 0..63
            int d = (it * 4 + (tid & 3)) * 4; // 0..124
            float4 v;
            v.x = ts[(d + 0) * 65 + e];
            v.y = ts[(d + 1) * 65 + e];
            v.z = ts[(d + 2) * 65 + e];
            v.w = ts[(d + 3) * 65 + e];
            *reinterpret_cast<float4*>(
                out + ((size_t)b * ND + ecol0 + e) * ND + di * 128 + d) = v;
        }
        __syncthreads();
        // D: out_i[e][d] = -D[d][e]
#pragma unroll
        for (int mt = 0; mt < 2; mt++) {
            int gdl = wm * 32 + mt * 16 + (lane >> 2);
#pragma unroll
            for (int nt = 0; nt < 4; nt++) {
                int gel = wn * 32 + nt * 8 + (lane & 3) * 2;
                ts[gdl * 65 + gel]           = accD[mt][nt][0];
                ts[gdl * 65 + gel + 1]       = accD[mt][nt][1];
                ts[(gdl + 8) * 65 + gel]     = accD[mt][nt][2];
                ts[(gdl + 8) * 65 + gel + 1] = accD[mt][nt][3];
            }
        }
        __syncthreads();
#pragma unroll
        for (int it = 0; it < 8; it++) {
            int e = tid >> 2;
            int d = (it * 4 + (tid & 3)) * 4;
            float4 v;
            v.x = -ts[(d + 0) * 65 + e];
            v.y = -ts[(d + 1) * 65 + e];
            v.z = -ts[(d + 2) * 65 + e];
            v.w = -ts[(d + 3) * 65 + e];
            *reinterpret_cast<float4*>(
                out + ob + ((size_t)b * ND + ecol0 + e) * ND + di * 128 + d) = v;
        }
    }
}

extern "C" void kernel_launch(void* const* d_in, const int* in_sizes, int n_in,
                              void* d_out, int out_size) {
    const float* real = (const float*)d_in[0];
    const float* imag = (const float*)d_in[1];
    const float* weight = (const float*)d_in[2];
    float* out = (float*)d_out;

    cudaFuncSetAttribute(gemm_kernel, cudaFuncAttributeMaxDynamicSharedMemorySize, SMEM_REQ);

    prep_kernel<<<NB * NT, 128>>>(real, imag, weight);

    dim3 g2(20, 1, NB);  // 12 off-diag halves + 8 diag halves, x 64 batches
    gemm_kernel<<<g2, 256, SMEM_REQ>>>(out);
}